// round 2
// baseline (speedup 1.0000x reference)
#include <cuda_runtime.h>

#define Bq 4
#define Vq 50000
#define Cq 160

// G table: per node-column c, 12 components j (9 for M = R rows, 3 for t),
// each with 4 batch values packed consecutively: g_table[c*48 + j*4 + b].
// Aligned 16 so it can be read as ulonglong2 (f32x2 pairs).
__device__ __align__(16) float g_table[Cq * 48];

// ---------------- Precompute kernel: 640 threads total ----------------
__global__ void precompute_kernel(const float* __restrict__ X,
                                  const float* __restrict__ Vn,
                                  const float* __restrict__ r6,
                                  const int* __restrict__ idx) {
    int i = blockIdx.x * blockDim.x + threadIdx.x;
    if (i >= Bq * Cq) return;
    int b = i / Cq, c = i % Cq;

    const float* d6 = r6 + (size_t)(b * Cq + c) * 6;
    float a1x = d6[0], a1y = d6[1], a1z = d6[2];
    float a2x = d6[3], a2y = d6[4], a2z = d6[5];

    float n1 = fmaxf(sqrtf(a1x*a1x + a1y*a1y + a1z*a1z), 1e-8f);
    float b1x = a1x / n1, b1y = a1y / n1, b1z = a1z / n1;
    float dt = b1x*a2x + b1y*a2y + b1z*a2z;
    float px = a2x - dt*b1x, py = a2y - dt*b1y, pz = a2z - dt*b1z;
    float n2 = fmaxf(sqrtf(px*px + py*py + pz*pz), 1e-8f);
    float b2x = px / n2, b2y = py / n2, b2z = pz / n2;
    float b3x = b1y*b2z - b1z*b2y;
    float b3y = b1z*b2x - b1x*b2z;
    float b3z = b1x*b2y - b1y*b2x;

    float R[3][3] = {{b1x, b1y, b1z}, {b2x, b2y, b2z}, {b3x, b3y, b3z}};

    int vi = idx[c];
    // clamp defensively (reference guarantees 0 <= vi < V)
    vi = max(0, min(Vq - 1, vi));
    const float* xc = X + ((size_t)b * Vq + vi) * 3;
    float cen[3] = {xc[0], xc[1], xc[2]};
    const float* vn = Vn + (size_t)(b * Cq + c) * 3;

    #pragma unroll
    for (int k = 0; k < 3; k++) {
        float t = cen[k] + vn[k]
                - (R[k][0]*cen[0] + R[k][1]*cen[1] + R[k][2]*cen[2]);
        g_table[c*48 + (9 + k)*4 + b] = t;
        #pragma unroll
        for (int d = 0; d < 3; d++)
            g_table[c*48 + (k*3 + d)*4 + b] = R[k][d];
    }
}

// ---------------- f32x2 helpers ----------------
__device__ __forceinline__ void fma2(unsigned long long& acc,
                                     unsigned long long a,
                                     unsigned long long b) {
    asm("fma.rn.f32x2 %0, %1, %2, %0;" : "+l"(acc) : "l"(a), "l"(b));
}
__device__ __forceinline__ unsigned long long dup2(float w) {
    unsigned long long r;
    asm("mov.b64 %0, {%1, %1};" : "=l"(r) : "f"(w));
    return r;
}
__device__ __forceinline__ float2 unpk(unsigned long long a) {
    float2 r;
    asm("mov.b64 {%0, %1}, %2;" : "=f"(r.x), "=f"(r.y) : "l"(a));
    return r;
}

// ---------------- Epilogue: out[b,v,:] = M·x + t ----------------
__device__ __forceinline__ void finish(int v,
                                       const unsigned long long* aA,
                                       const unsigned long long* aB,
                                       const float* __restrict__ X,
                                       float* __restrict__ out) {
    #pragma unroll
    for (int b = 0; b < 4; b++) {
        float m[12];
        #pragma unroll
        for (int j = 0; j < 12; j++) {
            float2 u = unpk((b < 2) ? aA[j] : aB[j]);
            m[j] = (b & 1) ? u.y : u.x;
        }
        const float* xp = X + ((size_t)b * Vq + v) * 3;
        float x0 = xp[0], x1 = xp[1], x2 = xp[2];
        float* op = out + ((size_t)b * Vq + v) * 3;
        #pragma unroll
        for (int k = 0; k < 3; k++)
            op[k] = m[9 + k] + m[3*k]*x0 + m[3*k + 1]*x1 + m[3*k + 2]*x2;
    }
}

// ---------------- Main kernel: 2 vertices per thread ----------------
__global__ void __launch_bounds__(64)
main_kernel(const float* __restrict__ W,
            const float* __restrict__ X,
            float* __restrict__ out) {
    // G staged in smem as packed f32x2 pairs: sg[c*24 + j*2 + p]
    __shared__ __align__(16) unsigned long long sg[Cq * 24];
    {
        const unsigned long long* g2 = (const unsigned long long*)g_table;
        for (int i = threadIdx.x; i < Cq * 24; i += 64) sg[i] = g2[i];
    }
    __syncthreads();

    int t = blockIdx.x * 64 + threadIdx.x;
    int v0 = 2 * t, v1 = 2 * t + 1;
    if (v0 >= Vq) return;

    unsigned long long accA0[12], accB0[12], accA1[12], accB1[12];
    #pragma unroll
    for (int j = 0; j < 12; j++) {
        accA0[j] = 0ull; accB0[j] = 0ull;
        accA1[j] = 0ull; accB1[j] = 0ull;
    }

    const float4* w0 = (const float4*)(W + (size_t)v0 * Cq);
    const float4* w1 = (const float4*)(W + (size_t)v1 * Cq);

    #pragma unroll 2
    for (int cq = 0; cq < Cq / 4; cq++) {
        float4 wa = w0[cq];
        float4 wb = w1[cq];
        float wa_s[4] = {wa.x, wa.y, wa.z, wa.w};
        float wb_s[4] = {wb.x, wb.y, wb.z, wb.w};
        #pragma unroll
        for (int s = 0; s < 4; s++) {
            unsigned long long W0d = dup2(wa_s[s]);
            unsigned long long W1d = dup2(wb_s[s]);
            const ulonglong2* gr =
                (const ulonglong2*)&sg[(cq * 4 + s) * 24];
            #pragma unroll
            for (int j = 0; j < 12; j++) {
                ulonglong2 g = gr[j];          // g.x=(b0,b1), g.y=(b2,b3)
                fma2(accA0[j], W0d, g.x);
                fma2(accB0[j], W0d, g.y);
                fma2(accA1[j], W1d, g.x);
                fma2(accB1[j], W1d, g.y);
            }
        }
    }

    finish(v0, accA0, accB0, X, out);
    finish(v1, accA1, accB1, X, out);
}

// ---------------- launch ----------------
extern "C" void kernel_launch(void* const* d_in, const int* in_sizes, int n_in,
                              void* d_out, int out_size) {
    const float* X   = (const float*)d_in[0];
    const float* Vn  = (const float*)d_in[1];
    const float* r6  = (const float*)d_in[2];
    const float* W   = (const float*)d_in[3];
    const int*   idx = (const int*)d_in[4];   // JAX x64-disabled: int64 -> int32
    float* out = (float*)d_out;

    precompute_kernel<<<(Bq * Cq + 127) / 128, 128>>>(X, Vn, r6, idx);

    int nthreads = Vq / 2;                    // 2 vertices per thread
    int grid = (nthreads + 63) / 64;          // 391 blocks
    main_kernel<<<grid, 64>>>(W, X, out);
}